// round 17
// baseline (speedup 1.0000x reference)
#include <cuda_runtime.h>
#include <cuda_fp16.h>
#include <cstdint>

#define H 128

// ---------------------------------------------------------------------------
// Global scratch (no allocations allowed)
// ---------------------------------------------------------------------------
// Per-node layer-1 partials in fp16: [gd_gene | gd_dis | gg_src | gg_dst]
__device__ __half g_Ph[42000000];
// fp16 weights (rounded), transposed: [part][n][k]
// part: 0 = w1_gd[:128], 1 = w1_gg[:128], 2 = w1_gg[128:], 3 = w1_gd[128:]
__device__ __half g_Wh[4 * H * H];
// fp16 layer-2 weights: [rel][H]  (rel 0 = gd, 1 = gg)
__device__ __half g_W2h[2 * H];

// ---------------------------------------------------------------------------
// helpers
// ---------------------------------------------------------------------------
__device__ __forceinline__ uint32_t smem_u32(const void* p){
    uint32_t a;
    asm("{ .reg .u64 t; cvta.to.shared.u64 t, %1; cvt.u32.u64 %0, t; }" : "=r"(a) : "l"(p));
    return a;
}
__device__ __forceinline__ void ldsm4(uint32_t* r, uint32_t addr){
    asm volatile("ldmatrix.sync.aligned.m8n8.x4.shared.b16 {%0,%1,%2,%3}, [%4];"
        : "=r"(r[0]), "=r"(r[1]), "=r"(r[2]), "=r"(r[3]) : "r"(addr));
}
__device__ __forceinline__ void mma_f16(float* d, const uint32_t* a,
                                        uint32_t b0, uint32_t b1){
    asm volatile("mma.sync.aligned.m16n8k16.row.col.f32.f16.f16.f32 "
        "{%0,%1,%2,%3}, {%4,%5,%6,%7}, {%8,%9}, {%0,%1,%2,%3};"
        : "+f"(d[0]), "+f"(d[1]), "+f"(d[2]), "+f"(d[3])
        : "r"(a[0]), "r"(a[1]), "r"(a[2]), "r"(a[3]), "r"(b0), "r"(b1));
}

// XOR-swizzled byte offset inside a [128 rows x 128 fp16] tile (256B rows).
__device__ __forceinline__ uint32_t toff(int r, int kc){
    return (uint32_t)r * 256u + (uint32_t)((kc ^ (r & 7)) << 4);
}

// smem map: A 32KB | B 32KB
#define SM_A  0
#define SM_B  32768
#define SM_TOTAL 65536

// ---------------------------------------------------------------------------
// Kernel 0: round+transpose the four 128x128 W1 blocks -> fp16 [n][k];
// also round the two w2 vectors -> fp16.
// ---------------------------------------------------------------------------
__global__ void prep_w_kernel(const float* __restrict__ w1_gd,
                              const float* __restrict__ w1_gg,
                              const float* __restrict__ w2_gd,
                              const float* __restrict__ w2_gg)
{
    int idx = blockIdx.x * blockDim.x + threadIdx.x;  // 4*128*128 + 256
    if (idx < 4 * H * H) {
        int part = idx >> 14;
        int n = (idx >> 7) & 127;
        int k = idx & 127;
        const float* Wsrc = (part == 0) ? w1_gd
                          : (part == 1) ? w1_gg
                          : (part == 2) ? (w1_gg + H * H)
                                        : (w1_gd + H * H);
        g_Wh[((size_t)part * H + n) * H + k] = __float2half_rn(Wsrc[k * H + n]);
    } else if (idx < 4 * H * H + 2 * H) {
        int i2 = idx - 4 * H * H;
        int rel = i2 >> 7, n = i2 & 127;
        g_W2h[rel * H + n] = __float2half_rn((rel ? w2_gg : w2_gd)[n]);
    }
}

// ---------------------------------------------------------------------------
// Kernel 1: single-pass fp16 GEMM (fp32 acc), 512 threads, 16 warps x 32x32.
// A staged once; gene tiles loop parts 0,1,2; disease tiles part 3.
// (bit-identical to the round-8 GEMM)
// ---------------------------------------------------------------------------
__global__ void __launch_bounds__(512, 2)
gemm_tc_kernel(const float* __restrict__ zg, const float* __restrict__ zd,
               const float* __restrict__ b1_gd, const float* __restrict__ b1_gg,
               int n_gene, int n_dis)
{
    extern __shared__ char smem[];
    const uint32_t sb = smem_u32(smem);
    const int tid = threadIdx.x;

    const int tg = (n_gene + 127) >> 7;
    const size_t ng = (size_t)n_gene * H, nd = (size_t)n_dis * H;

    const int b = blockIdx.x;
    const bool isGene = (b < tg);
    const float* A = isGene ? zg : zd;
    const int M = isGene ? n_gene : n_dis;
    const int m0 = (isGene ? b : (b - tg)) << 7;
    const int nparts = isGene ? 3 : 1;

    // ---- stage A (fp32 -> fp16) once: 2048 16B chunks, 4 per thread ----
    #pragma unroll
    for (int i = 0; i < 4; i++) {
        int u = tid + 512 * i;
        int r = u >> 4, c8 = u & 15;
        float4 v0 = make_float4(0.f,0.f,0.f,0.f), v1 = v0;
        if (m0 + r < M) {
            const float* ap = &A[(size_t)(m0 + r) * H + c8 * 8];
            v0 = *(const float4*)ap;
            v1 = *(const float4*)(ap + 4);
        }
        __half2 h0 = __floats2half2_rn(v0.x, v0.y);
        __half2 h1 = __floats2half2_rn(v0.z, v0.w);
        __half2 h2 = __floats2half2_rn(v1.x, v1.y);
        __half2 h3 = __floats2half2_rn(v1.z, v1.w);
        uint4 pk = make_uint4(*(uint32_t*)&h0, *(uint32_t*)&h1,
                              *(uint32_t*)&h2, *(uint32_t*)&h3);
        *(uint4*)(smem + SM_A + toff(r, c8)) = pk;
    }

    const int lane = tid & 31, w = tid >> 5;
    const int wr = w >> 2, wc = w & 3;          // 4x4 warp grid, 32x32 tiles
    const int arow = wr * 32 + (lane & 15);
    const int akh  = lane >> 4;
    const int brow = wc * 32 + (lane & 7) + ((lane >> 4) << 3);
    const int bkh  = (lane >> 3) & 1;
    const int rbase = m0 + wr * 32 + (lane >> 2);
    const int cbase = wc * 32 + (lane & 3) * 2;

    for (int p = 0; p < nparts; p++) {
        const int part = isGene ? p : 3;
        const float* bias = (part == 2) ? b1_gg : (part == 3) ? b1_gd : nullptr;
        const size_t outOff = (part == 0) ? 0
                            : (part == 1) ? (ng + nd)
                            : (part == 2) ? (ng + nd + ng)
                                          : ng;

        // ---- stage B for this part: 2048 chunks, 4 per thread ----
        {
            const uint4* bp = (const uint4*)(g_Wh + (size_t)part * H * H);
            #pragma unroll
            for (int i = 0; i < 4; i++) {
                int u = tid + 512 * i;
                int r = u >> 4, kc = u & 15;
                *(uint4*)(smem + SM_B + toff(r, kc)) = bp[u];
            }
        }
        __syncthreads();

        // ---- compute: 32x32 warp tile ----
        float acc[2][4][4];
        #pragma unroll
        for (int mt = 0; mt < 2; mt++)
            #pragma unroll
            for (int nt = 0; nt < 4; nt++)
                #pragma unroll
                for (int q = 0; q < 4; q++) acc[mt][nt][q] = 0.f;

        #pragma unroll
        for (int s = 0; s < 8; s++) {
            uint32_t afr[2][4];
            #pragma unroll
            for (int mt = 0; mt < 2; mt++)
                ldsm4(afr[mt], sb + SM_A + toff(arow + mt * 16, 2 * s + akh));

            uint32_t bfr[2][4];
            #pragma unroll
            for (int np = 0; np < 2; np++)
                ldsm4(bfr[np], sb + SM_B + toff(brow + np * 16, 2 * s + bkh));

            #pragma unroll
            for (int mt = 0; mt < 2; mt++)
                #pragma unroll
                for (int nt = 0; nt < 4; nt++)
                    mma_f16(acc[mt][nt], afr[mt],
                            bfr[nt >> 1][(nt & 1) * 2], bfr[nt >> 1][(nt & 1) * 2 + 1]);
        }

        // ---- writeout (fp16) ----
        #pragma unroll
        for (int mt = 0; mt < 2; mt++) {
            #pragma unroll
            for (int nt = 0; nt < 4; nt++) {
                int n = cbase + nt * 8;
                float bx = 0.f, by = 0.f;
                if (bias) { float2 bv = *(const float2*)&bias[n]; bx = bv.x; by = bv.y; }
                int rr0 = rbase + mt * 16;
                int rr1 = rr0 + 8;
                if (rr0 < M) {
                    __half2 o0 = __floats2half2_rn(acc[mt][nt][0] + bx, acc[mt][nt][1] + by);
                    *(__half2*)&g_Ph[outOff + (size_t)rr0 * H + n] = o0;
                }
                if (rr1 < M) {
                    __half2 o1 = __floats2half2_rn(acc[mt][nt][2] + bx, acc[mt][nt][3] + by);
                    *(__half2*)&g_Ph[outOff + (size_t)rr1 * H + n] = o1;
                }
            }
        }
        if (p + 1 < nparts) __syncthreads();
    }
}

// ---------------------------------------------------------------------------
// Kernel 2: per-edge combine. Half-warp per edge, half2 add+relu, fp16 hfma2
// dot (8-deep per lane), fp32 butterfly. x2 ILP -> 4 edges/warp/iter.
// ---------------------------------------------------------------------------
__device__ __forceinline__ float edot8h(uint4 ua, uint4 ub, uint4 wh){
    const __half2 z = __half2half2(__ushort_as_half(0));
    __half2 h0 = __hmax2(__hadd2(*(__half2*)&ua.x, *(__half2*)&ub.x), z);
    __half2 h1 = __hmax2(__hadd2(*(__half2*)&ua.y, *(__half2*)&ub.y), z);
    __half2 h2 = __hmax2(__hadd2(*(__half2*)&ua.z, *(__half2*)&ub.z), z);
    __half2 h3 = __hmax2(__hadd2(*(__half2*)&ua.w, *(__half2*)&ub.w), z);
    __half2 acc = __hmul2(h0, *(__half2*)&wh.x);
    acc = __hfma2(h1, *(__half2*)&wh.y, acc);
    acc = __hfma2(h2, *(__half2*)&wh.z, acc);
    acc = __hfma2(h3, *(__half2*)&wh.w, acc);
    float2 f = __half22float2(acc);
    return f.x + f.y;
}

__global__ void __launch_bounds__(256)
edge_decode_kernel(const int* __restrict__ edges_gd, const int* __restrict__ edges_gg,
                   const float* __restrict__ b2_gd, const float* __restrict__ b2_gg,
                   float* __restrict__ out, int E, int n_gene, int n_dis)
{
    const int rel = blockIdx.y;
    const size_t ng = (size_t)n_gene * H;
    const size_t nd = (size_t)n_dis * H;

    const int*   edges = rel ? edges_gg : edges_gd;
    const __half* Psrc = rel ? (g_Ph + ng + nd)      : g_Ph;
    const __half* Pdst = rel ? (g_Ph + ng + nd + ng) : (g_Ph + ng);
    const float  b2    = (rel ? b2_gg : b2_gd)[0];
    float* o = out + (size_t)rel * E;

    const int lane   = threadIdx.x & 31;
    const int warp   = (blockIdx.x * blockDim.x + threadIdx.x) >> 5;
    const int nwarps = (gridDim.x * blockDim.x) >> 5;
    const int hl  = lane >> 4;       // half-warp id (0/1)
    const int sub = lane & 15;       // lane within half-warp

    const uint4 wh = *(const uint4*)&g_W2h[rel * H + sub * 8];
    const uint4 zero4 = make_uint4(0u, 0u, 0u, 0u);

    for (int base = 2 * warp; base < E; base += 4 * nwarps) {
        const int eA = base + hl;
        const int eB = base + 2 * nwarps + hl;
        const bool hasA = eA < E;
        const bool hasB = eB < E;

        uint4 a0 = zero4, b0 = zero4, a1 = zero4, b1 = zero4;
        if (hasA) {
            const int s = edges[eA], d = edges[E + eA];
            a0 = *(const uint4*)&Psrc[(size_t)s * H + sub * 8];
            b0 = *(const uint4*)&Pdst[(size_t)d * H + sub * 8];
        }
        if (hasB) {
            const int s = edges[eB], d = edges[E + eB];
            a1 = *(const uint4*)&Psrc[(size_t)s * H + sub * 8];
            b1 = *(const uint4*)&Pdst[(size_t)d * H + sub * 8];
        }

        float sA = edot8h(a0, b0, wh);
        float sB = edot8h(a1, b1, wh);

        // butterfly within each 16-lane half (xor offsets < 16)
        #pragma unroll
        for (int off = 8; off; off >>= 1) {
            sA += __shfl_xor_sync(0xFFFFFFFFu, sA, off);
            sB += __shfl_xor_sync(0xFFFFFFFFu, sB, off);
        }

        if (sub == 0) {
            if (hasA) o[eA] = sA + b2;
            if (hasB) o[eB] = sB + b2;
        }
    }
}

// ---------------------------------------------------------------------------
extern "C" void kernel_launch(void* const* d_in, const int* in_sizes, int n_in,
                              void* d_out, int out_size)
{
    const float* z_gene = (const float*)d_in[0];
    const float* z_dis  = (const float*)d_in[1];
    const int*   e_gd   = (const int*)  d_in[2];
    const int*   e_gg   = (const int*)  d_in[3];
    const float* w1_gd  = (const float*)d_in[4];
    const float* b1_gd  = (const float*)d_in[5];
    const float* w2_gd  = (const float*)d_in[6];
    const float* b2_gd  = (const float*)d_in[7];
    const float* w1_gg  = (const float*)d_in[8];
    const float* b1_gg  = (const float*)d_in[9];
    const float* w2_gg  = (const float*)d_in[10];
    const float* b2_gg  = (const float*)d_in[11];

    const int n_gene = in_sizes[0] / H;
    const int n_dis  = in_sizes[1] / H;
    const int E      = in_sizes[2] / 2;

    static bool init_done = false;
    if (!init_done) {
        cudaFuncSetAttribute(gemm_tc_kernel,
                             cudaFuncAttributeMaxDynamicSharedMemorySize, SM_TOTAL);
        init_done = true;
    }

    prep_w_kernel<<<(4 * H * H + 2 * H + 255) / 256, 256>>>(w1_gd, w1_gg,
                                                            w2_gd, w2_gg);

    const int tg = (n_gene + 127) >> 7;
    const int td = (n_dis + 127) >> 7;
    gemm_tc_kernel<<<tg + td, 512, SM_TOTAL>>>(z_gene, z_dis, b1_gd, b1_gg,
                                               n_gene, n_dis);

    dim3 egrid(1184, 2);
    edge_decode_kernel<<<egrid, 256>>>(e_gd, e_gg, b2_gd, b2_gg,
                                       (float*)d_out, E, n_gene, n_dis);
}